// round 2
// baseline (speedup 1.0000x reference)
#include <cuda_runtime.h>
#include <math.h>

// Problem constants
#define HD    768
#define NH    8
#define HEAD  96
#define NB    2
#define HH    128
#define WWW   128
#define HW    16384        // 128*128
#define PTOT  (NB*HW)      // 32768

// ---------------- scratch (static device globals; no allocation) ----------------
__device__ float g_s1[NB*HD];
__device__ float g_s2[NB*HD];
__device__ float g_s3[NB*HD];
__device__ float g_qkv[(size_t)NB*3*HD*HW];   // [b, 2304, h, w]
__device__ float g_abuf[(size_t)NB*HD*HW];    // attention output, [b, 768, h, w]
__device__ float g_x2[(size_t)NB*HD*HW];      // residual after attention
__device__ float g_m1[(size_t)4*HD*PTOT];     // gelu(fc1) as [o=3072][p=32768]
__device__ float g_m2[(size_t)NB*HD*HW];      // fc2 out [b, 768, h, w]

// ---------------- per-(b,c) RMS-instance scale: w[c] / (std_unbiased + 1e-8) ----
__global__ void std_scale_kernel(const float* __restrict__ X,
                                 const float* __restrict__ w,
                                 float* __restrict__ sout)
{
    __shared__ float rs[256], rq[256];
    int bc = blockIdx.x;
    const float* p = X + (size_t)bc * HW;
    float s = 0.f, q = 0.f;
    for (int i = threadIdx.x; i < HW; i += 256) {
        float v = p[i];
        s += v; q += v * v;
    }
    rs[threadIdx.x] = s; rq[threadIdx.x] = q;
    __syncthreads();
    for (int off = 128; off; off >>= 1) {
        if (threadIdx.x < off) {
            rs[threadIdx.x] += rs[threadIdx.x + off];
            rq[threadIdx.x] += rq[threadIdx.x + off];
        }
        __syncthreads();
    }
    if (threadIdx.x == 0) {
        float sum = rs[0], sq = rq[0];
        float var = (sq - sum * sum * (1.0f / (float)HW)) * (1.0f / (float)(HW - 1));
        float sd = sqrtf(fmaxf(var, 0.f));
        int c = bc % HD;
        sout[bc] = w[c] / (sd + 1e-8f);
    }
}

// ---------------- generic SGEMM: Out[o,p] = sum_k Wm[o,k] * In[k,p] -------------
// In index  = b*in_sb + k*in_sk + hw         (per-position activations)
// Out index = b*out_sb + o*out_sk + hw
// optional: iscale[b*K+k] multiplies the input column (fused RMS-IN norm)
// epilogue:  v = acc + bias[o]; if gelu: exact gelu; if gamma: v = v*gamma[o] + resid[outidx]
__global__ void __launch_bounds__(256)
gemm_kernel(const float* __restrict__ Wm, const float* __restrict__ In,
            float* __restrict__ Out,
            const float* __restrict__ bias, const float* __restrict__ iscale,
            const float* __restrict__ gamma, const float* __restrict__ resid,
            int M, int K, int in_sk, int in_sb, int out_sk, int out_sb,
            int act_gelu)
{
    __shared__ float As[8][128];
    __shared__ float Bs[8][128];
    int m0 = blockIdx.x * 128, p0 = blockIdx.y * 128;
    int b = p0 >> 14, hw0 = p0 & 16383;
    int tid = threadIdx.x;
    int tx = tid & 15, ty = tid >> 4;

    float acc[8][8];
#pragma unroll
    for (int r = 0; r < 8; r++)
#pragma unroll
        for (int s = 0; s < 8; s++) acc[r][s] = 0.f;

    int arow = tid >> 1, acol = (tid & 1) * 4;
    int brow = tid >> 5, bcol = (tid & 31) * 4;
    const float* inb  = In + (size_t)b * in_sb + hw0;
    const float* wrow = Wm + (size_t)(m0 + arow) * K + acol;

    for (int k0 = 0; k0 < K; k0 += 8) {
        float4 av = *(const float4*)(wrow + k0);
        As[acol + 0][arow] = av.x;
        As[acol + 1][arow] = av.y;
        As[acol + 2][arow] = av.z;
        As[acol + 3][arow] = av.w;
        float4 bv = *(const float4*)(inb + (size_t)(k0 + brow) * in_sk + bcol);
        if (iscale) {
            float sc = iscale[b * K + k0 + brow];
            bv.x *= sc; bv.y *= sc; bv.z *= sc; bv.w *= sc;
        }
        *(float4*)&Bs[brow][bcol] = bv;
        __syncthreads();
#pragma unroll
        for (int kk = 0; kk < 8; kk++) {
            float4 a0 = *(float4*)&As[kk][ty * 8];
            float4 a1 = *(float4*)&As[kk][ty * 8 + 4];
            float4 b0 = *(float4*)&Bs[kk][tx * 8];
            float4 b1 = *(float4*)&Bs[kk][tx * 8 + 4];
            float a[8]  = {a0.x, a0.y, a0.z, a0.w, a1.x, a1.y, a1.z, a1.w};
            float bb[8] = {b0.x, b0.y, b0.z, b0.w, b1.x, b1.y, b1.z, b1.w};
#pragma unroll
            for (int r = 0; r < 8; r++)
#pragma unroll
                for (int s = 0; s < 8; s++) acc[r][s] += a[r] * bb[s];
        }
        __syncthreads();
    }

#pragma unroll
    for (int r = 0; r < 8; r++) {
        int o = m0 + ty * 8 + r;
        float bi = bias ? bias[o] : 0.f;
        float gm = gamma ? gamma[o] : 0.f;
        size_t ob = (size_t)b * out_sb + (size_t)o * out_sk + hw0 + tx * 8;
        float v[8];
#pragma unroll
        for (int s = 0; s < 8; s++) {
            float t = acc[r][s] + bi;
            if (act_gelu) t = 0.5f * t * (1.f + erff(t * 0.70710678118654752f));
            v[s] = t;
        }
        if (gamma) {
            float4 r0 = *(const float4*)(resid + ob);
            float4 r1 = *(const float4*)(resid + ob + 4);
            v[0] = v[0] * gm + r0.x; v[1] = v[1] * gm + r0.y;
            v[2] = v[2] * gm + r0.z; v[3] = v[3] * gm + r0.w;
            v[4] = v[4] * gm + r1.x; v[5] = v[5] * gm + r1.y;
            v[6] = v[6] * gm + r1.z; v[7] = v[7] * gm + r1.w;
        }
        float4 o0 = {v[0], v[1], v[2], v[3]};
        float4 o1 = {v[4], v[5], v[6], v[7]};
        *(float4*)(Out + ob)     = o0;
        *(float4*)(Out + ob + 4) = o1;
    }
}

// ---------------- axial attention, one block per (b, head, line) ----------------
// axis==0: attention along W for fixed h (positions contiguous)
// axis==1: attention along H for fixed w (positions strided by 128); accumulates
#define SROW 129
__global__ void __launch_bounds__(256)
attn_axis_kernel(const float* __restrict__ qkv, float* __restrict__ abuf,
                 const float* __restrict__ qn_w, const float* __restrict__ qn_b,
                 const float* __restrict__ kn_w, const float* __restrict__ kn_b,
                 int axis)
{
    extern __shared__ float sm[];
    float* qs = sm;                  // [96][129]
    float* ks = sm + 96 * SROW;      // [96][129]
    float* ss = sm + 2 * 96 * SROW;  // [128][129]

    int blk = blockIdx.x;
    int fix = blk & 127;
    int he  = (blk >> 7) & 7;
    int b   = blk >> 10;
    int tid = threadIdx.x;

    size_t qbase  = ((size_t)(b * 2304 + he * 288) << 14) + (axis ? fix : fix * 128);
    int istride   = axis ? 128 : 1;

    // load q, k tiles (c-major)
    for (int idx = tid; idx < 96 * 128; idx += 256) {
        int c = idx >> 7, i = idx & 127;
        size_t g = qbase + ((size_t)c << 14) + (size_t)i * istride;
        qs[c * SROW + i] = qkv[g];
        ks[c * SROW + i] = qkv[g + ((size_t)96 << 14)];
    }
    __syncthreads();

    // fused LayerNorm over HEAD dim (ddof=0, eps=1e-5): warps 0-3 -> q, 4-7 -> k
    {
        int pos = tid & 127;
        float* t        = (tid < 128) ? qs : ks;
        const float* lw = (tid < 128) ? qn_w : kn_w;
        const float* lb = (tid < 128) ? qn_b : kn_b;
        float s = 0.f, q = 0.f;
        for (int c = 0; c < 96; c++) {
            float v = t[c * SROW + pos];
            s += v; q += v * v;
        }
        float mu  = s * (1.f / 96.f);
        float var = q * (1.f / 96.f) - mu * mu;
        float inv = rsqrtf(var + 1e-5f);
        for (int c = 0; c < 96; c++)
            t[c * SROW + pos] = (t[c * SROW + pos] - mu) * inv * lw[c] + lb[c];
    }
    __syncthreads();

    // scores[i][j] = scale * sum_c q[c][i] * k[c][j]
    int tx = tid & 15, ty = tid >> 4;
    {
        float acc[8][8];
#pragma unroll
        for (int r = 0; r < 8; r++)
#pragma unroll
            for (int s = 0; s < 8; s++) acc[r][s] = 0.f;
        for (int c = 0; c < 96; c++) {
            float a[8], bb[8];
#pragma unroll
            for (int r = 0; r < 8; r++) a[r]  = qs[c * SROW + ty * 8 + r];
#pragma unroll
            for (int s = 0; s < 8; s++) bb[s] = ks[c * SROW + tx * 8 + s];
#pragma unroll
            for (int r = 0; r < 8; r++)
#pragma unroll
                for (int s = 0; s < 8; s++) acc[r][s] += a[r] * bb[s];
        }
        const float sc = 0.102062072615966f;  // 1/sqrt(96)
#pragma unroll
        for (int r = 0; r < 8; r++)
#pragma unroll
            for (int s = 0; s < 8; s++)
                ss[(ty * 8 + r) * SROW + tx * 8 + s] = acc[r][s] * sc;
    }
    __syncthreads();

    // softmax over j (rows of ss), one warp per row group
    {
        int warp = tid >> 5, lane = tid & 31;
        for (int i = warp; i < 128; i += 8) {
            float* row = ss + i * SROW;
            float v0 = row[lane], v1 = row[lane + 32], v2 = row[lane + 64], v3 = row[lane + 96];
            float m = fmaxf(fmaxf(v0, v1), fmaxf(v2, v3));
#pragma unroll
            for (int o = 16; o; o >>= 1) m = fmaxf(m, __shfl_xor_sync(0xffffffffu, m, o));
            float e0 = expf(v0 - m), e1 = expf(v1 - m), e2 = expf(v2 - m), e3 = expf(v3 - m);
            float su = e0 + e1 + e2 + e3;
#pragma unroll
            for (int o = 16; o; o >>= 1) su += __shfl_xor_sync(0xffffffffu, su, o);
            float inv = 1.f / su;
            row[lane] = e0 * inv; row[lane + 32] = e1 * inv;
            row[lane + 64] = e2 * inv; row[lane + 96] = e3 * inv;
        }
    }
    // v tile into the (now free) q region
    float* vs = qs;
    for (int idx = tid; idx < 96 * 128; idx += 256) {
        int c = idx >> 7, i = idx & 127;
        vs[c * SROW + i] = qkv[qbase + ((size_t)(192 + c) << 14) + (size_t)i * istride];
    }
    __syncthreads();

    // out[i][c] = sum_j P[i][j] * v[c][j]; thread: 8 i's x 6 c's
    {
        float oacc[8][6];
#pragma unroll
        for (int r = 0; r < 8; r++)
#pragma unroll
            for (int s = 0; s < 6; s++) oacc[r][s] = 0.f;
        for (int j = 0; j < 128; j++) {
            float a[8], vv[6];
#pragma unroll
            for (int r = 0; r < 8; r++) a[r]  = ss[(ty * 8 + r) * SROW + j];
#pragma unroll
            for (int s = 0; s < 6; s++) vv[s] = vs[(tx * 6 + s) * SROW + j];
#pragma unroll
            for (int r = 0; r < 8; r++)
#pragma unroll
                for (int s = 0; s < 6; s++) oacc[r][s] += a[r] * vv[s];
        }
        size_t ob = ((size_t)(b * 768 + he * 96) << 14) + (axis ? fix : fix * 128);
        if (axis == 0) {
#pragma unroll
            for (int s = 0; s < 6; s++)
#pragma unroll
                for (int r = 0; r < 8; r++)
                    abuf[ob + ((size_t)(tx * 6 + s) << 14) + (ty * 8 + r)] = 0.5f * oacc[r][s];
        } else {
#pragma unroll
            for (int s = 0; s < 6; s++)
#pragma unroll
                for (int r = 0; r < 8; r++) {
                    size_t g = ob + ((size_t)(tx * 6 + s) << 14) + (size_t)(ty * 8 + r) * 128;
                    abuf[g] = abuf[g] + 0.5f * oacc[r][s];
                }
        }
    }
}

// ---------------- final: out = x2 + gamma_mlp[c] * m2 * s3[b,c] -----------------
__global__ void final_kernel(float* __restrict__ out, const float* __restrict__ x2,
                             const float* __restrict__ m2, const float* __restrict__ s3,
                             const float* __restrict__ gmlp)
{
    int idx = blockIdx.x * 256 + threadIdx.x;
    int bc = idx >> 14;
    int c  = bc % HD;
    out[idx] = x2[idx] + gmlp[c] * m2[idx] * s3[bc];
}

// ---------------- launch --------------------------------------------------------
extern "C" void kernel_launch(void* const* d_in, const int* in_sizes, int n_in,
                              void* d_out, int out_size)
{
    const float* x         = (const float*)d_in[0];
    const float* norm1_w   = (const float*)d_in[1];
    const float* qkv_w     = (const float*)d_in[2];
    const float* qkv_b     = (const float*)d_in[3];
    const float* qn_w      = (const float*)d_in[4];
    const float* qn_b      = (const float*)d_in[5];
    const float* kn_w      = (const float*)d_in[6];
    const float* kn_b      = (const float*)d_in[7];
    const float* norm2_w   = (const float*)d_in[8];
    const float* out_w     = (const float*)d_in[9];
    const float* out_b     = (const float*)d_in[10];
    const float* gamma_att = (const float*)d_in[11];
    const float* fc1_w     = (const float*)d_in[12];
    const float* fc1_b     = (const float*)d_in[13];
    const float* fc2_w     = (const float*)d_in[14];
    const float* fc2_b     = (const float*)d_in[15];
    const float* mlp_nw    = (const float*)d_in[16];
    const float* gamma_mlp = (const float*)d_in[17];
    float* out = (float*)d_out;

    float *s1, *s2p, *s3p, *qkvb, *ab, *x2b, *m1b, *m2b;
    cudaGetSymbolAddress((void**)&s1,   g_s1);
    cudaGetSymbolAddress((void**)&s2p,  g_s2);
    cudaGetSymbolAddress((void**)&s3p,  g_s3);
    cudaGetSymbolAddress((void**)&qkvb, g_qkv);
    cudaGetSymbolAddress((void**)&ab,   g_abuf);
    cudaGetSymbolAddress((void**)&x2b,  g_x2);
    cudaGetSymbolAddress((void**)&m1b,  g_m1);
    cudaGetSymbolAddress((void**)&m2b,  g_m2);

    const int SMEMB = (2 * 96 * SROW + 128 * SROW) * 4;  // 165120 bytes
    cudaFuncSetAttribute(attn_axis_kernel,
                         cudaFuncAttributeMaxDynamicSharedMemorySize, SMEMB);

    // 1) norm1 scale
    std_scale_kernel<<<NB * HD, 256>>>(x, norm1_w, s1);

    // 2) qkv projection (norm fused into input scale)
    gemm_kernel<<<dim3(2304 / 128, PTOT / 128), 256>>>(
        qkv_w, x, qkvb, qkv_b, s1, nullptr, nullptr,
        2304, 768, HW, 768 * HW, HW, 2304 * HW, 0);

    // 3) axial attention (LN on q,k fused)
    attn_axis_kernel<<<NB * NH * 128, 256, SMEMB>>>(qkvb, ab, qn_w, qn_b, kn_w, kn_b, 0);
    attn_axis_kernel<<<NB * NH * 128, 256, SMEMB>>>(qkvb, ab, qn_w, qn_b, kn_w, kn_b, 1);

    // 4) norm2 scale
    std_scale_kernel<<<NB * HD, 256>>>(ab, norm2_w, s2p);

    // 5) out projection + gamma_att * . + residual(x)  -> x2
    gemm_kernel<<<dim3(768 / 128, PTOT / 128), 256>>>(
        out_w, ab, x2b, out_b, s2p, gamma_att, x,
        768, 768, HW, 768 * HW, HW, 768 * HW, 0);

    // 6) fc1 + exact GELU -> m1  ([3072][32768])
    gemm_kernel<<<dim3(3072 / 128, PTOT / 128), 256>>>(
        fc1_w, x2b, m1b, fc1_b, nullptr, nullptr, nullptr,
        3072, 768, HW, 768 * HW, PTOT, HW, 1);

    // 7) fc2 -> m2 ([b,768,h,w])
    gemm_kernel<<<dim3(768 / 128, PTOT / 128), 256>>>(
        fc2_w, m1b, m2b, fc2_b, nullptr, nullptr, nullptr,
        768, 3072, PTOT, HW, HW, 768 * HW, 0);

    // 8) mlp norm scale
    std_scale_kernel<<<NB * HD, 256>>>(m2b, mlp_nw, s3p);

    // 9) final residual combine
    final_kernel<<<(NB * HD * HW) / 256, 256>>>(out, x2b, m2b, s3p, gamma_mlp);
}